// round 9
// baseline (speedup 1.0000x reference)
#include <cuda_runtime.h>
#include <cuda_fp16.h>
#include <cstdint>

#define D_F 16

// ---- global prepped weight image (fp16 hi/lo) ----
// Per field d (2048 B at d*2048):
//   +0    : W1, 4 tiles 8x8 f16: [hi n0-7][hi n8-15][lo n0-7][lo n8-15]
//           row=n, col=k: k<3 -> W1[d][n][k], k==3 -> b1[d][n], else 0
//   +512  : W2, 8 tiles: hi{(n0,k0),(n0,k1),(n1,k0),(n1,k1)} then lo same; W2[d][g][h]
//   +1536 : W3, 4 tiles: [hi k0][hi k1][lo k0][lo k1]; row=o (0 pad o>=3), col=h
// b2 f32 [16][16] at 32768, b3 padded f32 [16][8] at 33792.
#define B2_OFF 32768
#define B3_OFF 33792
#define IMG_BYTES 34304

__device__ __align__(16) unsigned char g_img[IMG_BYTES];

// ============ prep kernel ============
__global__ void prep_kernel(const float* __restrict__ W1, const float* __restrict__ b1,
                            const float* __restrict__ W2, const float* __restrict__ b2,
                            const float* __restrict__ W3, const float* __restrict__ b3)
{
    int i = blockIdx.x * blockDim.x + threadIdx.x;
    unsigned short* wimg = (unsigned short*)g_img;
    if (i < 8192) {
        int d = i >> 9;
        int w = i & 511;
        int fb = d * 1024;
        float v = 0.0f;
        int hi_idx, lo_idx;
        if (w < 128) {                    // W1 (+ b1 in k=3 column)
            int s = w, tile = s >> 6, rr = (s >> 3) & 7, cc = s & 7;
            int n = tile * 8 + rr;
            if (cc < 3)       v = W1[d * 48 + n * 3 + cc];
            else if (cc == 3) v = b1[d * 16 + n];
            hi_idx = fb + s;        lo_idx = fb + 128 + s;
        } else if (w < 384) {             // W2
            int s = w - 128, tt = s >> 6, rr = (s >> 3) & 7, cc = s & 7;
            int nt = tt >> 1, kt = tt & 1;
            v = W2[d * 256 + (nt * 8 + rr) * 16 + (kt * 8 + cc)];
            hi_idx = fb + 256 + s;  lo_idx = fb + 512 + s;
        } else {                          // W3
            int s = w - 384, kt = s >> 6, rr = (s >> 3) & 7, cc = s & 7;
            v = (rr < 3) ? W3[d * 48 + rr * 16 + (kt * 8 + cc)] : 0.0f;
            hi_idx = fb + 768 + s;  lo_idx = fb + 896 + s;
        }
        __half hv = __float2half_rn(v);
        float res = v - __half2float(hv);
        __half lv = __float2half_rn(res);
        wimg[hi_idx] = reinterpret_cast<unsigned short&>(hv);
        wimg[lo_idx] = reinterpret_cast<unsigned short&>(lv);
    } else if (i < 8192 + 256) {
        int j = i - 8192;
        ((float*)(g_img + B2_OFF))[j] = b2[j];
    } else if (i < 8192 + 256 + 128) {
        int j = i - 8448;
        int d = j >> 3, o = j & 7;
        ((float*)(g_img + B3_OFF))[j] = (o < 3) ? b3[d * 3 + o] : 0.0f;
    }
}

// ============ mma / cvt helpers (fp16) ============
__device__ __forceinline__ void ldsm4(unsigned& r0, unsigned& r1, unsigned& r2, unsigned& r3,
                                      unsigned a) {
    asm volatile("ldmatrix.sync.aligned.m8n8.x4.shared.b16 {%0,%1,%2,%3}, [%4];"
                 : "=r"(r0), "=r"(r1), "=r"(r2), "=r"(r3) : "r"(a));
}
__device__ __forceinline__ void mma_k8(float c[4], unsigned a0, unsigned a1, unsigned b0) {
    asm volatile("mma.sync.aligned.m16n8k8.row.col.f32.f16.f16.f32 "
                 "{%0,%1,%2,%3}, {%4,%5}, {%6}, {%0,%1,%2,%3};"
                 : "+f"(c[0]), "+f"(c[1]), "+f"(c[2]), "+f"(c[3])
                 : "r"(a0), "r"(a1), "r"(b0));
}
__device__ __forceinline__ void mma_k16(float c[4], const unsigned a[4], unsigned b0, unsigned b1) {
    asm volatile("mma.sync.aligned.m16n8k16.row.col.f32.f16.f16.f32 "
                 "{%0,%1,%2,%3}, {%4,%5,%6,%7}, {%8,%9}, {%0,%1,%2,%3};"
                 : "+f"(c[0]), "+f"(c[1]), "+f"(c[2]), "+f"(c[3])
                 : "r"(a[0]), "r"(a[1]), "r"(a[2]), "r"(a[3]), "r"(b0), "r"(b1));
}
__device__ __forceinline__ unsigned cvt2(float v0, float v1) {
    unsigned h;
    asm("cvt.rn.f16x2.f32 %0, %1, %2;" : "=r"(h) : "f"(v1), "f"(v0));
    return h;
}
__device__ __forceinline__ unsigned cvt2_relu(float v0, float v1) {
    unsigned h = cvt2(v0, v1);
    unsigned r;
    asm("max.f16x2 %0, %1, %2;" : "=r"(r) : "r"(h), "r"(0u));
    return r;
}

// ============ main kernel: one FIELD per warp, weights resident in registers ============
// grid 1064 x 128 threads = 4256 warps = 266 warp-groups of 16 fields.
__global__ __launch_bounds__(128, 6)
void fields_mma_kernel(const float* __restrict__ x, float* __restrict__ out, int N)
{
    __shared__ __align__(16) unsigned char smem[IMG_BYTES];
    {
        const uint4* src = (const uint4*)g_img;
        uint4* dst = (uint4*)smem;
        for (int i = threadIdx.x; i < IMG_BYTES / 16; i += blockDim.x) dst[i] = src[i];
    }
    __syncthreads();

    const unsigned sbase = (unsigned)__cvta_generic_to_shared(smem);
    const float* sB2 = (const float*)(smem + B2_OFF);
    const float* sB3 = (const float*)(smem + B3_OFF);

    const int tid  = threadIdx.x;
    const int wid  = tid >> 5, lane = tid & 31;
    const int q    = lane & 3, r = lane >> 2;
    const unsigned lm_off = ((unsigned)(lane >> 3) << 7) + ((unsigned)(lane & 7) << 4);

    const int gwarp   = blockIdx.x * 4 + wid;
    const int nwarps  = gridDim.x * 4;        // must be multiple of 16
    const int d       = gwarp & 15;           // this warp's field, fixed
    const int tile0   = gwarp >> 4;
    const int tstride = nwarps >> 4;
    const int ntiles  = (N + 31) >> 5;        // 32 points per tile

    // ---- load this field's weights ONCE into registers ----
    const unsigned fbase = sbase + (unsigned)(d * 2048);
    unsigned w1h0, w1h1, w1l0, w1l1;
    ldsm4(w1h0, w1h1, w1l0, w1l1, fbase + lm_off);
    unsigned w2h0, w2h1, w2h2, w2h3, w2l0, w2l1, w2l2, w2l3;
    ldsm4(w2h0, w2h1, w2h2, w2h3, fbase + 512 + lm_off);
    ldsm4(w2l0, w2l1, w2l2, w2l3, fbase + 1024 + lm_off);
    unsigned w3h0, w3h1, w3d0, w3d1;          // lo fragments loaded but unused (dropped)
    ldsm4(w3h0, w3h1, w3d0, w3d1, fbase + 1536 + lm_off);

    const float2 bn0 = *(const float2*)&sB2[d * 16 + 2 * q];
    const float2 bn1 = *(const float2*)&sB2[d * 16 + 8 + 2 * q];
    const float2 b3v = *(const float2*)&sB3[d * 8 + 2 * q];

    // output row pointers for this warp's (d, o) pairs
    const int o0 = 2 * q, o1 = 2 * q + 1;
    float* row0 = (o0 < 3) ? out + (size_t)(d * 3 + o0) * N : nullptr;
    float* row1 = (o1 < 3) ? out + (size_t)(d * 3 + o1) * N : nullptr;

    for (int tile = tile0; tile < ntiles; tile += tstride) {
        const int P = tile << 5;
        const int pA0 = P + r,      pA1 = P + r + 8;
        const int pB0 = P + r + 16, pB1 = P + r + 24;
        const bool iA0 = pA0 < N, iA1 = pA1 < N, iB0 = pB0 < N, iB1 = pB1 < N;

        // ---- x A-fragments (single fp16): k = {x0,x1,x2,1,0,0,0,0} ----
        float a00 = 0.f, a01 = 0.f, a10 = 0.f, a11 = 0.f;
        float b00 = 0.f, b01 = 0.f, b10 = 0.f, b11 = 0.f;
        if (q == 0) {
            if (iA0) { a00 = x[pA0]; a01 = x[N + pA0]; }
            if (iA1) { a10 = x[pA1]; a11 = x[N + pA1]; }
            if (iB0) { b00 = x[pB0]; b01 = x[N + pB0]; }
            if (iB1) { b10 = x[pB1]; b11 = x[N + pB1]; }
        } else if (q == 1) {
            if (iA0) { a00 = x[2 * N + pA0]; a01 = 1.0f; }
            if (iA1) { a10 = x[2 * N + pA1]; a11 = 1.0f; }
            if (iB0) { b00 = x[2 * N + pB0]; b01 = 1.0f; }
            if (iB1) { b10 = x[2 * N + pB1]; b11 = 1.0f; }
        }
        const unsigned xA0 = cvt2(a00, a01), xA1 = cvt2(a10, a11);
        const unsigned xB0 = cvt2(b00, b01), xB1 = cvt2(b10, b11);

        // ================= layer 1 (A single fp16, W hi+lo) =================
        float cA0[4] = {0, 0, 0, 0}, cA1[4] = {0, 0, 0, 0};
        float cB0[4] = {0, 0, 0, 0}, cB1[4] = {0, 0, 0, 0};
        mma_k8(cA0, xA0, xA1, w1h0);  mma_k8(cB0, xB0, xB1, w1h0);
        mma_k8(cA1, xA0, xA1, w1h1);  mma_k8(cB1, xB0, xB1, w1h1);
        mma_k8(cA0, xA0, xA1, w1l0);  mma_k8(cB0, xB0, xB1, w1l0);
        mma_k8(cA1, xA0, xA1, w1l1);  mma_k8(cB1, xB0, xB1, w1l1);

        unsigned aA[4], aB[4];
        aA[0] = cvt2_relu(cA0[0], cA0[1]);  aA[1] = cvt2_relu(cA0[2], cA0[3]);
        aA[2] = cvt2_relu(cA1[0], cA1[1]);  aA[3] = cvt2_relu(cA1[2], cA1[3]);
        aB[0] = cvt2_relu(cB0[0], cB0[1]);  aB[1] = cvt2_relu(cB0[2], cB0[3]);
        aB[2] = cvt2_relu(cB1[0], cB1[1]);  aB[3] = cvt2_relu(cB1[2], cB1[3]);

        // ================= layer 2 =================
        float eA0[4] = {bn0.x, bn0.y, bn0.x, bn0.y};
        float eA1[4] = {bn1.x, bn1.y, bn1.x, bn1.y};
        float eB0[4] = {bn0.x, bn0.y, bn0.x, bn0.y};
        float eB1[4] = {bn1.x, bn1.y, bn1.x, bn1.y};
        mma_k16(eA0, aA, w2h0, w2h1);  mma_k16(eB0, aB, w2h0, w2h1);
        mma_k16(eA1, aA, w2h2, w2h3);  mma_k16(eB1, aB, w2h2, w2h3);
        mma_k16(eA0, aA, w2l0, w2l1);  mma_k16(eB0, aB, w2l0, w2l1);
        mma_k16(eA1, aA, w2l2, w2l3);  mma_k16(eB1, aB, w2l2, w2l3);

        unsigned gA[4], gB[4];
        gA[0] = cvt2_relu(eA0[0], eA0[1]);  gA[1] = cvt2_relu(eA0[2], eA0[3]);
        gA[2] = cvt2_relu(eA1[0], eA1[1]);  gA[3] = cvt2_relu(eA1[2], eA1[3]);
        gB[0] = cvt2_relu(eB0[0], eB0[1]);  gB[1] = cvt2_relu(eB0[2], eB0[3]);
        gB[2] = cvt2_relu(eB1[0], eB1[1]);  gB[3] = cvt2_relu(eB1[2], eB1[3]);

        // ================= layer 3 (hi only; lo compensation dropped) =================
        float fA[4] = {b3v.x, b3v.y, b3v.x, b3v.y};
        float fB[4] = {b3v.x, b3v.y, b3v.x, b3v.y};
        mma_k16(fA, gA, w3h0, w3h1);  mma_k16(fB, gB, w3h0, w3h1);

        // ---- store ----
        if (row0) {
            if (iA0) row0[pA0] = fA[0];
            if (iA1) row0[pA1] = fA[2];
            if (iB0) row0[pB0] = fB[0];
            if (iB1) row0[pB1] = fB[2];
        }
        if (row1) {
            if (iA0) row1[pA0] = fA[1];
            if (iA1) row1[pA1] = fA[3];
            if (iB0) row1[pB0] = fB[1];
            if (iB1) row1[pB1] = fB[3];
        }
    }
}

extern "C" void kernel_launch(void* const* d_in, const int* in_sizes, int n_in,
                              void* d_out, int out_size)
{
    const float* x  = (const float*)d_in[0];
    const float* W1 = (const float*)d_in[1];
    const float* b1 = (const float*)d_in[2];
    const float* W2 = (const float*)d_in[3];
    const float* b2 = (const float*)d_in[4];
    const float* W3 = (const float*)d_in[5];
    const float* b3 = (const float*)d_in[6];
    float* out = (float*)d_out;

    const int N = in_sizes[0] / 3;   // x is [1,3,N]

    prep_kernel<<<(8576 + 255) / 256, 256>>>(W1, b1, W2, b2, W3, b3);

    // 6 CTAs/SM x 128 threads; 1064*4 = 4256 warps (multiple of 16 fields)
    fields_mma_kernel<<<1064, 128>>>(x, out, N);
}

// round 10
// speedup vs baseline: 1.3331x; 1.3331x over previous
#include <cuda_runtime.h>
#include <cuda_fp16.h>
#include <cstdint>

#define D_F 16

// ---- global prepped weight image (fp16 hi/lo) ----
// Per field d (2048 B at d*2048):
//   +0    : W1, 4 tiles 8x8 f16: [hi n0-7][hi n8-15][lo n0-7][lo n8-15]
//           row=n, col=k: k<3 -> W1[d][n][k], k==3 -> b1[d][n], else 0
//   +512  : W2, 8 tiles: hi{(n0,k0),(n0,k1),(n1,k0),(n1,k1)} then lo same; W2[d][g][h]
//   +1536 : W3, 4 tiles: [hi k0][hi k1][lo k0][lo k1]; row=o (0 pad o>=3), col=h
// b2 f32 [16][16] at 32768, b3 padded f32 [16][8] at 33792.
#define B2_OFF 32768
#define B3_OFF 33792
#define IMG_BYTES 34304

__device__ __align__(16) unsigned char g_img[IMG_BYTES];

// ============ prep kernel ============
__global__ void prep_kernel(const float* __restrict__ W1, const float* __restrict__ b1,
                            const float* __restrict__ W2, const float* __restrict__ b2,
                            const float* __restrict__ W3, const float* __restrict__ b3)
{
    int i = blockIdx.x * blockDim.x + threadIdx.x;
    unsigned short* wimg = (unsigned short*)g_img;
    if (i < 8192) {
        int d = i >> 9;
        int w = i & 511;
        int fb = d * 1024;
        float v = 0.0f;
        int hi_idx, lo_idx;
        if (w < 128) {                    // W1 (+ b1 in k=3 column)
            int s = w, tile = s >> 6, rr = (s >> 3) & 7, cc = s & 7;
            int n = tile * 8 + rr;
            if (cc < 3)       v = W1[d * 48 + n * 3 + cc];
            else if (cc == 3) v = b1[d * 16 + n];
            hi_idx = fb + s;        lo_idx = fb + 128 + s;
        } else if (w < 384) {             // W2
            int s = w - 128, tt = s >> 6, rr = (s >> 3) & 7, cc = s & 7;
            int nt = tt >> 1, kt = tt & 1;
            v = W2[d * 256 + (nt * 8 + rr) * 16 + (kt * 8 + cc)];
            hi_idx = fb + 256 + s;  lo_idx = fb + 512 + s;
        } else {                          // W3
            int s = w - 384, kt = s >> 6, rr = (s >> 3) & 7, cc = s & 7;
            v = (rr < 3) ? W3[d * 48 + rr * 16 + (kt * 8 + cc)] : 0.0f;
            hi_idx = fb + 768 + s;  lo_idx = fb + 896 + s;
        }
        __half hv = __float2half_rn(v);
        float res = v - __half2float(hv);
        __half lv = __float2half_rn(res);
        wimg[hi_idx] = reinterpret_cast<unsigned short&>(hv);
        wimg[lo_idx] = reinterpret_cast<unsigned short&>(lv);
    } else if (i < 8192 + 256) {
        int j = i - 8192;
        ((float*)(g_img + B2_OFF))[j] = b2[j];
    } else if (i < 8192 + 256 + 128) {
        int j = i - 8448;
        int d = j >> 3, o = j & 7;
        ((float*)(g_img + B3_OFF))[j] = (o < 3) ? b3[d * 3 + o] : 0.0f;
    }
}

// ============ mma / cvt helpers (fp16) ============
__device__ __forceinline__ void ldsm4(unsigned& r0, unsigned& r1, unsigned& r2, unsigned& r3,
                                      unsigned a) {
    asm volatile("ldmatrix.sync.aligned.m8n8.x4.shared.b16 {%0,%1,%2,%3}, [%4];"
                 : "=r"(r0), "=r"(r1), "=r"(r2), "=r"(r3) : "r"(a));
}
__device__ __forceinline__ void ldsm2(unsigned& r0, unsigned& r1, unsigned a) {
    asm volatile("ldmatrix.sync.aligned.m8n8.x2.shared.b16 {%0,%1}, [%2];"
                 : "=r"(r0), "=r"(r1) : "r"(a));
}
__device__ __forceinline__ void mma_k8(float c[4], unsigned a0, unsigned a1, unsigned b0) {
    asm volatile("mma.sync.aligned.m16n8k8.row.col.f32.f16.f16.f32 "
                 "{%0,%1,%2,%3}, {%4,%5}, {%6}, {%0,%1,%2,%3};"
                 : "+f"(c[0]), "+f"(c[1]), "+f"(c[2]), "+f"(c[3])
                 : "r"(a0), "r"(a1), "r"(b0));
}
__device__ __forceinline__ void mma_k16(float c[4], const unsigned a[4], unsigned b0, unsigned b1) {
    asm volatile("mma.sync.aligned.m16n8k16.row.col.f32.f16.f16.f32 "
                 "{%0,%1,%2,%3}, {%4,%5,%6,%7}, {%8,%9}, {%0,%1,%2,%3};"
                 : "+f"(c[0]), "+f"(c[1]), "+f"(c[2]), "+f"(c[3])
                 : "r"(a[0]), "r"(a[1]), "r"(a[2]), "r"(a[3]), "r"(b0), "r"(b1));
}
__device__ __forceinline__ unsigned cvt2(float v0, float v1) {
    unsigned h;
    asm("cvt.rn.f16x2.f32 %0, %1, %2;" : "=r"(h) : "f"(v1), "f"(v0));
    return h;
}
__device__ __forceinline__ unsigned cvt2_relu(float v0, float v1) {
    unsigned h = cvt2(v0, v1);
    unsigned r;
    asm("max.f16x2 %0, %1, %2;" : "=r"(r) : "r"(h), "r"(0u));
    return r;
}

// weight-fragment load macro (14 regs per buffer; W3 hi-only via ldsm.x2)
#define LDW(PFX, DIDX) do {                                                   \
    unsigned _fb = sbase + ((unsigned)(DIDX) * 2048u) + lm_off;               \
    ldsm4(PFX##w1h0, PFX##w1h1, PFX##w1l0, PFX##w1l1, _fb);                   \
    ldsm4(PFX##w2h0, PFX##w2h1, PFX##w2h2, PFX##w2h3, _fb + 512);             \
    ldsm4(PFX##w2l0, PFX##w2l1, PFX##w2l2, PFX##w2l3, _fb + 1024);            \
    ldsm2(PFX##w3h0, PFX##w3h1, _fb + 1536);                                  \
} while (0)

// ============ main kernel: 2 point-tiles/warp, pipelined per-field weights ============
__global__ __launch_bounds__(128, 6)
void fields_mma_kernel(const float* __restrict__ x, float* __restrict__ out, int N)
{
    __shared__ __align__(16) unsigned char smem[IMG_BYTES];
    {
        const uint4* src = (const uint4*)g_img;
        uint4* dst = (uint4*)smem;
        for (int i = threadIdx.x; i < IMG_BYTES / 16; i += blockDim.x) dst[i] = src[i];
    }
    __syncthreads();

    const unsigned sbase = (unsigned)__cvta_generic_to_shared(smem);
    const float* sB2 = (const float*)(smem + B2_OFF);
    const float* sB3 = (const float*)(smem + B3_OFF);

    const int tid  = threadIdx.x;
    const int wid  = tid >> 5, lane = tid & 31;
    const int q    = lane & 3, r = lane >> 2;
    const unsigned lm_off = ((unsigned)(lane >> 3) << 7) + ((unsigned)(lane & 7) << 4);
    const int o0 = 2 * q, o1 = 2 * q + 1;

    const int gwarp  = blockIdx.x * 4 + wid;
    const int nwarps = gridDim.x * 4;
    const int ntiles = (N + 31) >> 5;            // 32 points per tile

    for (int tile = gwarp; tile < ntiles; tile += nwarps) {
        const int P = tile << 5;
        const int pA0 = P + r,      pA1 = P + r + 8;
        const int pB0 = P + r + 16, pB1 = P + r + 24;
        const bool iA0 = pA0 < N, iA1 = pA1 < N, iB0 = pB0 < N, iB1 = pB1 < N;

        // ---- x A-fragments (single fp16): k = {x0,x1,x2,1,0,0,0,0} ----
        float a00 = 0.f, a01 = 0.f, a10 = 0.f, a11 = 0.f;
        float b00 = 0.f, b01 = 0.f, b10 = 0.f, b11 = 0.f;
        if (q == 0) {
            if (iA0) { a00 = x[pA0]; a01 = x[N + pA0]; }
            if (iA1) { a10 = x[pA1]; a11 = x[N + pA1]; }
            if (iB0) { b00 = x[pB0]; b01 = x[N + pB0]; }
            if (iB1) { b10 = x[pB1]; b11 = x[N + pB1]; }
        } else if (q == 1) {
            if (iA0) { a00 = x[2 * N + pA0]; a01 = 1.0f; }
            if (iA1) { a10 = x[2 * N + pA1]; a11 = 1.0f; }
            if (iB0) { b00 = x[2 * N + pB0]; b01 = 1.0f; }
            if (iB1) { b10 = x[2 * N + pB1]; b11 = 1.0f; }
        }
        const unsigned xA0 = cvt2(a00, a01), xA1 = cvt2(a10, a11);
        const unsigned xB0 = cvt2(b00, b01), xB1 = cvt2(b10, b11);

        // one-field compute on a 14-register weight set
        auto do_field = [&](int d,
                            unsigned w1h0, unsigned w1h1, unsigned w1l0, unsigned w1l1,
                            unsigned w2h0, unsigned w2h1, unsigned w2h2, unsigned w2h3,
                            unsigned w2l0, unsigned w2l1, unsigned w2l2, unsigned w2l3,
                            unsigned w3h0, unsigned w3h1) {
            // ---- layer 1 ----
            float cA0[4] = {0, 0, 0, 0}, cA1[4] = {0, 0, 0, 0};
            float cB0[4] = {0, 0, 0, 0}, cB1[4] = {0, 0, 0, 0};
            mma_k8(cA0, xA0, xA1, w1h0);  mma_k8(cB0, xB0, xB1, w1h0);
            mma_k8(cA1, xA0, xA1, w1h1);  mma_k8(cB1, xB0, xB1, w1h1);
            mma_k8(cA0, xA0, xA1, w1l0);  mma_k8(cB0, xB0, xB1, w1l0);
            mma_k8(cA1, xA0, xA1, w1l1);  mma_k8(cB1, xB0, xB1, w1l1);

            unsigned aA[4], aB[4];
            aA[0] = cvt2_relu(cA0[0], cA0[1]);  aA[1] = cvt2_relu(cA0[2], cA0[3]);
            aA[2] = cvt2_relu(cA1[0], cA1[1]);  aA[3] = cvt2_relu(cA1[2], cA1[3]);
            aB[0] = cvt2_relu(cB0[0], cB0[1]);  aB[1] = cvt2_relu(cB0[2], cB0[3]);
            aB[2] = cvt2_relu(cB1[0], cB1[1]);  aB[3] = cvt2_relu(cB1[2], cB1[3]);

            // ---- layer 2 ----
            float2 bn0 = *(const float2*)&sB2[d * 16 + 2 * q];
            float2 bn1 = *(const float2*)&sB2[d * 16 + 8 + 2 * q];
            float eA0[4] = {bn0.x, bn0.y, bn0.x, bn0.y};
            float eA1[4] = {bn1.x, bn1.y, bn1.x, bn1.y};
            float eB0[4] = {bn0.x, bn0.y, bn0.x, bn0.y};
            float eB1[4] = {bn1.x, bn1.y, bn1.x, bn1.y};
            mma_k16(eA0, aA, w2h0, w2h1);  mma_k16(eB0, aB, w2h0, w2h1);
            mma_k16(eA1, aA, w2h2, w2h3);  mma_k16(eB1, aB, w2h2, w2h3);
            mma_k16(eA0, aA, w2l0, w2l1);  mma_k16(eB0, aB, w2l0, w2l1);
            mma_k16(eA1, aA, w2l2, w2l3);  mma_k16(eB1, aB, w2l2, w2l3);

            unsigned gA[4], gB[4];
            gA[0] = cvt2_relu(eA0[0], eA0[1]);  gA[1] = cvt2_relu(eA0[2], eA0[3]);
            gA[2] = cvt2_relu(eA1[0], eA1[1]);  gA[3] = cvt2_relu(eA1[2], eA1[3]);
            gB[0] = cvt2_relu(eB0[0], eB0[1]);  gB[1] = cvt2_relu(eB0[2], eB0[3]);
            gB[2] = cvt2_relu(eB1[0], eB1[1]);  gB[3] = cvt2_relu(eB1[2], eB1[3]);

            // ---- layer 3 (hi only) ----
            float2 b3v = *(const float2*)&sB3[d * 8 + 2 * q];
            float fA[4] = {b3v.x, b3v.y, b3v.x, b3v.y};
            float fB[4] = {b3v.x, b3v.y, b3v.x, b3v.y};
            mma_k16(fA, gA, w3h0, w3h1);  mma_k16(fB, gB, w3h0, w3h1);

            // ---- store ----
            if (o0 < 3) {
                float* rowp = out + (size_t)(d * 3 + o0) * N;
                if (iA0) rowp[pA0] = fA[0];
                if (iA1) rowp[pA1] = fA[2];
                if (iB0) rowp[pB0] = fB[0];
                if (iB1) rowp[pB1] = fB[2];
            }
            if (o1 < 3) {
                float* rowp = out + (size_t)(d * 3 + o1) * N;
                if (iA0) rowp[pA0] = fA[1];
                if (iA1) rowp[pA1] = fA[3];
                if (iB0) rowp[pB0] = fB[1];
                if (iB1) rowp[pB1] = fB[3];
            }
        };

        // ---- pipelined field loop: ping-pong weight buffers A/B ----
        unsigned Aw1h0, Aw1h1, Aw1l0, Aw1l1, Aw2h0, Aw2h1, Aw2h2, Aw2h3,
                 Aw2l0, Aw2l1, Aw2l2, Aw2l3, Aw3h0, Aw3h1;
        unsigned Bw1h0, Bw1h1, Bw1l0, Bw1l1, Bw2h0, Bw2h1, Bw2h2, Bw2h3,
                 Bw2l0, Bw2l1, Bw2l2, Bw2l3, Bw3h0, Bw3h1;

        LDW(A, 0);
        #pragma unroll 1
        for (int dd = 0; dd < D_F; dd += 2) {
            LDW(B, dd + 1);                  // prefetch odd field
            do_field(dd, Aw1h0, Aw1h1, Aw1l0, Aw1l1,
                     Aw2h0, Aw2h1, Aw2h2, Aw2h3, Aw2l0, Aw2l1, Aw2l2, Aw2l3,
                     Aw3h0, Aw3h1);
            LDW(A, (dd + 2) & 15);           // prefetch next even field (wraps harmlessly)
            do_field(dd + 1, Bw1h0, Bw1h1, Bw1l0, Bw1l1,
                     Bw2h0, Bw2h1, Bw2h2, Bw2h3, Bw2l0, Bw2l1, Bw2l2, Bw2l3,
                     Bw3h0, Bw3h1);
        }
    }
}

extern "C" void kernel_launch(void* const* d_in, const int* in_sizes, int n_in,
                              void* d_out, int out_size)
{
    const float* x  = (const float*)d_in[0];
    const float* W1 = (const float*)d_in[1];
    const float* b1 = (const float*)d_in[2];
    const float* W2 = (const float*)d_in[3];
    const float* b2 = (const float*)d_in[4];
    const float* W3 = (const float*)d_in[5];
    const float* b3 = (const float*)d_in[6];
    float* out = (float*)d_out;

    const int N = in_sizes[0] / 3;   // x is [1,3,N]

    prep_kernel<<<(8576 + 255) / 256, 256>>>(W1, b1, W2, b2, W3, b3);

    // 6 CTAs/SM x 128 threads on 152 SMs (grid-stride safe)
    fields_mma_kernel<<<912, 128>>>(x, out, N);
}

// round 11
// speedup vs baseline: 1.9766x; 1.4827x over previous
#include <cuda_runtime.h>
#include <cuda_fp16.h>
#include <cstdint>

#define D_F 16

// ---- global prepped weight image (fp16 hi/lo) ----
// Per field d (2048 B at d*2048):
//   +0    : W1, 4 tiles 8x8 f16: [hi n0-7][hi n8-15][lo n0-7][lo n8-15]
//           row=n, col=k: k<3 -> W1[d][n][k], k==3 -> b1[d][n], else 0
//   +512  : W2, 8 tiles: hi{(n0,k0),(n0,k1),(n1,k0),(n1,k1)} then lo same; W2[d][g][h]
//   +1536 : W3, 4 tiles: [hi k0][hi k1][lo k0][lo k1]; row=o (0 pad o>=3), col=h
// b2 f32 [16][16] at 32768, b3 padded f32 [16][8] at 33792.
#define B2_OFF 32768
#define B3_OFF 33792
#define IMG_BYTES 34304

__device__ __align__(16) unsigned char g_img[IMG_BYTES];

// ============ prep kernel ============
__global__ void prep_kernel(const float* __restrict__ W1, const float* __restrict__ b1,
                            const float* __restrict__ W2, const float* __restrict__ b2,
                            const float* __restrict__ W3, const float* __restrict__ b3)
{
    int i = blockIdx.x * blockDim.x + threadIdx.x;
    unsigned short* wimg = (unsigned short*)g_img;
    if (i < 8192) {
        int d = i >> 9;
        int w = i & 511;
        int fb = d * 1024;
        float v = 0.0f;
        int hi_idx, lo_idx;
        if (w < 128) {                    // W1 (+ b1 in k=3 column)
            int s = w, tile = s >> 6, rr = (s >> 3) & 7, cc = s & 7;
            int n = tile * 8 + rr;
            if (cc < 3)       v = W1[d * 48 + n * 3 + cc];
            else if (cc == 3) v = b1[d * 16 + n];
            hi_idx = fb + s;        lo_idx = fb + 128 + s;
        } else if (w < 384) {             // W2
            int s = w - 128, tt = s >> 6, rr = (s >> 3) & 7, cc = s & 7;
            int nt = tt >> 1, kt = tt & 1;
            v = W2[d * 256 + (nt * 8 + rr) * 16 + (kt * 8 + cc)];
            hi_idx = fb + 256 + s;  lo_idx = fb + 512 + s;
        } else {                          // W3
            int s = w - 384, kt = s >> 6, rr = (s >> 3) & 7, cc = s & 7;
            v = (rr < 3) ? W3[d * 48 + rr * 16 + (kt * 8 + cc)] : 0.0f;
            hi_idx = fb + 768 + s;  lo_idx = fb + 896 + s;
        }
        __half hv = __float2half_rn(v);
        float res = v - __half2float(hv);
        __half lv = __float2half_rn(res);
        wimg[hi_idx] = reinterpret_cast<unsigned short&>(hv);
        wimg[lo_idx] = reinterpret_cast<unsigned short&>(lv);
    } else if (i < 8192 + 256) {
        int j = i - 8192;
        ((float*)(g_img + B2_OFF))[j] = b2[j];
    } else if (i < 8192 + 256 + 128) {
        int j = i - 8448;
        int d = j >> 3, o = j & 7;
        ((float*)(g_img + B3_OFF))[j] = (o < 3) ? b3[d * 3 + o] : 0.0f;
    }
}

// ============ mma / cvt helpers (fp16) ============
__device__ __forceinline__ void ldsm4(unsigned& r0, unsigned& r1, unsigned& r2, unsigned& r3,
                                      unsigned a) {
    asm volatile("ldmatrix.sync.aligned.m8n8.x4.shared.b16 {%0,%1,%2,%3}, [%4];"
                 : "=r"(r0), "=r"(r1), "=r"(r2), "=r"(r3) : "r"(a));
}
__device__ __forceinline__ void ldsm2(unsigned& r0, unsigned& r1, unsigned a) {
    asm volatile("ldmatrix.sync.aligned.m8n8.x2.shared.b16 {%0,%1}, [%2];"
                 : "=r"(r0), "=r"(r1) : "r"(a));
}
__device__ __forceinline__ void mma_k8(float c[4], unsigned a0, unsigned a1, unsigned b0) {
    asm volatile("mma.sync.aligned.m16n8k8.row.col.f32.f16.f16.f32 "
                 "{%0,%1,%2,%3}, {%4,%5}, {%6}, {%0,%1,%2,%3};"
                 : "+f"(c[0]), "+f"(c[1]), "+f"(c[2]), "+f"(c[3])
                 : "r"(a0), "r"(a1), "r"(b0));
}
__device__ __forceinline__ void mma_k16(float c[4], const unsigned a[4], unsigned b0, unsigned b1) {
    asm volatile("mma.sync.aligned.m16n8k16.row.col.f32.f16.f16.f32 "
                 "{%0,%1,%2,%3}, {%4,%5,%6,%7}, {%8,%9}, {%0,%1,%2,%3};"
                 : "+f"(c[0]), "+f"(c[1]), "+f"(c[2]), "+f"(c[3])
                 : "r"(a[0]), "r"(a[1]), "r"(a[2]), "r"(a[3]), "r"(b0), "r"(b1));
}
__device__ __forceinline__ unsigned cvt2(float v0, float v1) {
    unsigned h;
    asm("cvt.rn.f16x2.f32 %0, %1, %2;" : "=r"(h) : "f"(v1), "f"(v0));
    return h;
}
__device__ __forceinline__ unsigned cvt2_relu(float v0, float v1) {
    unsigned h = cvt2(v0, v1);
    unsigned r;
    asm("max.f16x2 %0, %1, %2;" : "=r"(r) : "r"(h), "r"(0u));
    return r;
}

// ============ main kernel: 3 point-tiles (48 points) per warp iteration ============
__global__ __launch_bounds__(128, 6)
void fields_mma_kernel(const float* __restrict__ x, float* __restrict__ out, int N)
{
    __shared__ __align__(16) unsigned char smem[IMG_BYTES];
    {
        const uint4* src = (const uint4*)g_img;
        uint4* dst = (uint4*)smem;
        for (int i = threadIdx.x; i < IMG_BYTES / 16; i += blockDim.x) dst[i] = src[i];
    }
    __syncthreads();

    const unsigned sbase = (unsigned)__cvta_generic_to_shared(smem);
    const float* sB2 = (const float*)(smem + B2_OFF);
    const float* sB3 = (const float*)(smem + B3_OFF);

    const int tid  = threadIdx.x;
    const int wid  = tid >> 5, lane = tid & 31;
    const int q    = lane & 3, r = lane >> 2;
    const unsigned lm_off = ((unsigned)(lane >> 3) << 7) + ((unsigned)(lane & 7) << 4);

    const int gwarp  = blockIdx.x * 4 + wid;
    const int nwarps = gridDim.x * 4;
    const int ntiles = (N + 47) / 48;            // 48 points per tile

    for (int tile = gwarp; tile < ntiles; tile += nwarps) {
        const int P = tile * 48;
        const int pA0 = P + r,      pA1 = P + r + 8;
        const int pB0 = P + r + 16, pB1 = P + r + 24;
        const int pC0 = P + r + 32, pC1 = P + r + 40;
        const bool iA0 = pA0 < N, iA1 = pA1 < N, iB0 = pB0 < N, iB1 = pB1 < N;
        const bool iC0 = pC0 < N, iC1 = pC1 < N;

        // ---- x A-fragments (single fp16): k = {x0,x1,x2,1,0,0,0,0} ----
        float a00 = 0.f, a01 = 0.f, a10 = 0.f, a11 = 0.f;
        float b00 = 0.f, b01 = 0.f, b10 = 0.f, b11 = 0.f;
        float c00 = 0.f, c01 = 0.f, c10 = 0.f, c11 = 0.f;
        if (q == 0) {
            if (iA0) { a00 = x[pA0]; a01 = x[N + pA0]; }
            if (iA1) { a10 = x[pA1]; a11 = x[N + pA1]; }
            if (iB0) { b00 = x[pB0]; b01 = x[N + pB0]; }
            if (iB1) { b10 = x[pB1]; b11 = x[N + pB1]; }
            if (iC0) { c00 = x[pC0]; c01 = x[N + pC0]; }
            if (iC1) { c10 = x[pC1]; c11 = x[N + pC1]; }
        } else if (q == 1) {
            if (iA0) { a00 = x[2 * N + pA0]; a01 = 1.0f; }
            if (iA1) { a10 = x[2 * N + pA1]; a11 = 1.0f; }
            if (iB0) { b00 = x[2 * N + pB0]; b01 = 1.0f; }
            if (iB1) { b10 = x[2 * N + pB1]; b11 = 1.0f; }
            if (iC0) { c00 = x[2 * N + pC0]; c01 = 1.0f; }
            if (iC1) { c10 = x[2 * N + pC1]; c11 = 1.0f; }
        }
        const unsigned xA0 = cvt2(a00, a01), xA1 = cvt2(a10, a11);
        const unsigned xB0 = cvt2(b00, b01), xB1 = cvt2(b10, b11);
        const unsigned xC0 = cvt2(c00, c01), xC1 = cvt2(c10, c11);

        #pragma unroll 1
        for (int d = 0; d < D_F; d++) {
            const unsigned fbase = sbase + (unsigned)(d * 2048);

            // ================= layer 1 (A single fp16, W hi+lo) =================
            unsigned w1h0, w1h1, w1l0, w1l1;
            ldsm4(w1h0, w1h1, w1l0, w1l1, fbase + lm_off);
            float cA0[4] = {0, 0, 0, 0}, cA1[4] = {0, 0, 0, 0};
            float cB0[4] = {0, 0, 0, 0}, cB1[4] = {0, 0, 0, 0};
            float cC0[4] = {0, 0, 0, 0}, cC1[4] = {0, 0, 0, 0};
            mma_k8(cA0, xA0, xA1, w1h0);  mma_k8(cB0, xB0, xB1, w1h0);  mma_k8(cC0, xC0, xC1, w1h0);
            mma_k8(cA1, xA0, xA1, w1h1);  mma_k8(cB1, xB0, xB1, w1h1);  mma_k8(cC1, xC0, xC1, w1h1);
            mma_k8(cA0, xA0, xA1, w1l0);  mma_k8(cB0, xB0, xB1, w1l0);  mma_k8(cC0, xC0, xC1, w1l0);
            mma_k8(cA1, xA0, xA1, w1l1);  mma_k8(cB1, xB0, xB1, w1l1);  mma_k8(cC1, xC0, xC1, w1l1);

            unsigned aA[4], aB[4], aC[4];
            aA[0] = cvt2_relu(cA0[0], cA0[1]);  aA[1] = cvt2_relu(cA0[2], cA0[3]);
            aA[2] = cvt2_relu(cA1[0], cA1[1]);  aA[3] = cvt2_relu(cA1[2], cA1[3]);
            aB[0] = cvt2_relu(cB0[0], cB0[1]);  aB[1] = cvt2_relu(cB0[2], cB0[3]);
            aB[2] = cvt2_relu(cB1[0], cB1[1]);  aB[3] = cvt2_relu(cB1[2], cB1[3]);
            aC[0] = cvt2_relu(cC0[0], cC0[1]);  aC[1] = cvt2_relu(cC0[2], cC0[3]);
            aC[2] = cvt2_relu(cC1[0], cC1[1]);  aC[3] = cvt2_relu(cC1[2], cC1[3]);

            // ================= layer 2 =================
            unsigned w2h0, w2h1, w2h2, w2h3, w2l0, w2l1, w2l2, w2l3;
            ldsm4(w2h0, w2h1, w2h2, w2h3, fbase + 512 + lm_off);
            ldsm4(w2l0, w2l1, w2l2, w2l3, fbase + 1024 + lm_off);
            float2 bn0 = *(const float2*)&sB2[d * 16 + 2 * q];
            float2 bn1 = *(const float2*)&sB2[d * 16 + 8 + 2 * q];
            float eA0[4] = {bn0.x, bn0.y, bn0.x, bn0.y};
            float eA1[4] = {bn1.x, bn1.y, bn1.x, bn1.y};
            float eB0[4] = {bn0.x, bn0.y, bn0.x, bn0.y};
            float eB1[4] = {bn1.x, bn1.y, bn1.x, bn1.y};
            float eC0[4] = {bn0.x, bn0.y, bn0.x, bn0.y};
            float eC1[4] = {bn1.x, bn1.y, bn1.x, bn1.y};
            mma_k16(eA0, aA, w2h0, w2h1);  mma_k16(eB0, aB, w2h0, w2h1);  mma_k16(eC0, aC, w2h0, w2h1);
            mma_k16(eA1, aA, w2h2, w2h3);  mma_k16(eB1, aB, w2h2, w2h3);  mma_k16(eC1, aC, w2h2, w2h3);
            mma_k16(eA0, aA, w2l0, w2l1);  mma_k16(eB0, aB, w2l0, w2l1);  mma_k16(eC0, aC, w2l0, w2l1);
            mma_k16(eA1, aA, w2l2, w2l3);  mma_k16(eB1, aB, w2l2, w2l3);  mma_k16(eC1, aC, w2l2, w2l3);

            unsigned gA[4], gB[4], gC[4];
            gA[0] = cvt2_relu(eA0[0], eA0[1]);  gA[1] = cvt2_relu(eA0[2], eA0[3]);
            gA[2] = cvt2_relu(eA1[0], eA1[1]);  gA[3] = cvt2_relu(eA1[2], eA1[3]);
            gB[0] = cvt2_relu(eB0[0], eB0[1]);  gB[1] = cvt2_relu(eB0[2], eB0[3]);
            gB[2] = cvt2_relu(eB1[0], eB1[1]);  gB[3] = cvt2_relu(eB1[2], eB1[3]);
            gC[0] = cvt2_relu(eC0[0], eC0[1]);  gC[1] = cvt2_relu(eC0[2], eC0[3]);
            gC[2] = cvt2_relu(eC1[0], eC1[1]);  gC[3] = cvt2_relu(eC1[2], eC1[3]);

            // ================= layer 3 (hi only; lo dropped — validated R9/R10) ========
            unsigned w3h0, w3h1;
            ldsm2(w3h0, w3h1, fbase + 1536 + lm_off);
            float2 b3v = *(const float2*)&sB3[d * 8 + 2 * q];
            float fA[4] = {b3v.x, b3v.y, b3v.x, b3v.y};
            float fB[4] = {b3v.x, b3v.y, b3v.x, b3v.y};
            float fC[4] = {b3v.x, b3v.y, b3v.x, b3v.y};
            mma_k16(fA, gA, w3h0, w3h1);  mma_k16(fB, gB, w3h0, w3h1);  mma_k16(fC, gC, w3h0, w3h1);

            // ---- store ----
            const int o0 = 2 * q, o1 = 2 * q + 1;
            if (o0 < 3) {
                float* rowp = out + (size_t)(d * 3 + o0) * N;
                if (iA0) rowp[pA0] = fA[0];
                if (iA1) rowp[pA1] = fA[2];
                if (iB0) rowp[pB0] = fB[0];
                if (iB1) rowp[pB1] = fB[2];
                if (iC0) rowp[pC0] = fC[0];
                if (iC1) rowp[pC1] = fC[2];
            }
            if (o1 < 3) {
                float* rowp = out + (size_t)(d * 3 + o1) * N;
                if (iA0) rowp[pA0] = fA[1];
                if (iA1) rowp[pA1] = fA[3];
                if (iB0) rowp[pB0] = fB[1];
                if (iB1) rowp[pB1] = fB[3];
                if (iC0) rowp[pC0] = fC[1];
                if (iC1) rowp[pC1] = fC[3];
            }
        }
    }
}

extern "C" void kernel_launch(void* const* d_in, const int* in_sizes, int n_in,
                              void* d_out, int out_size)
{
    const float* x  = (const float*)d_in[0];
    const float* W1 = (const float*)d_in[1];
    const float* b1 = (const float*)d_in[2];
    const float* W2 = (const float*)d_in[3];
    const float* b2 = (const float*)d_in[4];
    const float* W3 = (const float*)d_in[5];
    const float* b3 = (const float*)d_in[6];
    float* out = (float*)d_out;

    const int N = in_sizes[0] / 3;   // x is [1,3,N]

    prep_kernel<<<(8576 + 255) / 256, 256>>>(W1, b1, W2, b2, W3, b3);

    // 6 CTAs/SM x 128 threads on 152 SMs (grid-stride safe)
    fields_mma_kernel<<<912, 128>>>(x, out, N);
}

// round 12
// speedup vs baseline: 2.7257x; 1.3790x over previous
#include <cuda_runtime.h>
#include <cuda_fp16.h>
#include <cstdint>

#define D_F 16

// ---- global prepped weight image (fp16 hi/lo; lo halves now unused) ----
// Per field d (2048 B at d*2048):
//   +0    : W1, 4 tiles 8x8 f16: [hi n0-7][hi n8-15][lo n0-7][lo n8-15]
//           row=n, col=k: k<3 -> W1[d][n][k], k==3 -> b1[d][n], else 0
//   +512  : W2, 8 tiles: hi{(n0,k0),(n0,k1),(n1,k0),(n1,k1)} then lo same; W2[d][g][h]
//   +1536 : W3, 4 tiles: [hi k0][hi k1][lo k0][lo k1]; row=o (0 pad o>=3), col=h
// b2 f32 [16][16] at 32768, b3 padded f32 [16][8] at 33792.
#define B2_OFF 32768
#define B3_OFF 33792
#define IMG_BYTES 34304

__device__ __align__(16) unsigned char g_img[IMG_BYTES];

// ============ prep kernel ============
__global__ void prep_kernel(const float* __restrict__ W1, const float* __restrict__ b1,
                            const float* __restrict__ W2, const float* __restrict__ b2,
                            const float* __restrict__ W3, const float* __restrict__ b3)
{
    int i = blockIdx.x * blockDim.x + threadIdx.x;
    unsigned short* wimg = (unsigned short*)g_img;
    if (i < 8192) {
        int d = i >> 9;
        int w = i & 511;
        int fb = d * 1024;
        float v = 0.0f;
        int hi_idx, lo_idx;
        if (w < 128) {                    // W1 (+ b1 in k=3 column)
            int s = w, tile = s >> 6, rr = (s >> 3) & 7, cc = s & 7;
            int n = tile * 8 + rr;
            if (cc < 3)       v = W1[d * 48 + n * 3 + cc];
            else if (cc == 3) v = b1[d * 16 + n];
            hi_idx = fb + s;        lo_idx = fb + 128 + s;
        } else if (w < 384) {             // W2
            int s = w - 128, tt = s >> 6, rr = (s >> 3) & 7, cc = s & 7;
            int nt = tt >> 1, kt = tt & 1;
            v = W2[d * 256 + (nt * 8 + rr) * 16 + (kt * 8 + cc)];
            hi_idx = fb + 256 + s;  lo_idx = fb + 512 + s;
        } else {                          // W3
            int s = w - 384, kt = s >> 6, rr = (s >> 3) & 7, cc = s & 7;
            v = (rr < 3) ? W3[d * 48 + rr * 16 + (kt * 8 + cc)] : 0.0f;
            hi_idx = fb + 768 + s;  lo_idx = fb + 896 + s;
        }
        __half hv = __float2half_rn(v);
        float res = v - __half2float(hv);
        __half lv = __float2half_rn(res);
        wimg[hi_idx] = reinterpret_cast<unsigned short&>(hv);
        wimg[lo_idx] = reinterpret_cast<unsigned short&>(lv);
    } else if (i < 8192 + 256) {
        int j = i - 8192;
        ((float*)(g_img + B2_OFF))[j] = b2[j];
    } else if (i < 8192 + 256 + 128) {
        int j = i - 8448;
        int d = j >> 3, o = j & 7;
        ((float*)(g_img + B3_OFF))[j] = (o < 3) ? b3[d * 3 + o] : 0.0f;
    }
}

// ============ mma / cvt helpers (fp16) ============
__device__ __forceinline__ void ldsm4(unsigned& r0, unsigned& r1, unsigned& r2, unsigned& r3,
                                      unsigned a) {
    asm volatile("ldmatrix.sync.aligned.m8n8.x4.shared.b16 {%0,%1,%2,%3}, [%4];"
                 : "=r"(r0), "=r"(r1), "=r"(r2), "=r"(r3) : "r"(a));
}
__device__ __forceinline__ void ldsm2(unsigned& r0, unsigned& r1, unsigned a) {
    asm volatile("ldmatrix.sync.aligned.m8n8.x2.shared.b16 {%0,%1}, [%2];"
                 : "=r"(r0), "=r"(r1) : "r"(a));
}
__device__ __forceinline__ void mma_k8(float c[4], unsigned a0, unsigned a1, unsigned b0) {
    asm volatile("mma.sync.aligned.m16n8k8.row.col.f32.f16.f16.f32 "
                 "{%0,%1,%2,%3}, {%4,%5}, {%6}, {%0,%1,%2,%3};"
                 : "+f"(c[0]), "+f"(c[1]), "+f"(c[2]), "+f"(c[3])
                 : "r"(a0), "r"(a1), "r"(b0));
}
__device__ __forceinline__ void mma_k16(float c[4], const unsigned a[4], unsigned b0, unsigned b1) {
    asm volatile("mma.sync.aligned.m16n8k16.row.col.f32.f16.f16.f32 "
                 "{%0,%1,%2,%3}, {%4,%5,%6,%7}, {%8,%9}, {%0,%1,%2,%3};"
                 : "+f"(c[0]), "+f"(c[1]), "+f"(c[2]), "+f"(c[3])
                 : "r"(a[0]), "r"(a[1]), "r"(a[2]), "r"(a[3]), "r"(b0), "r"(b1));
}
__device__ __forceinline__ unsigned cvt2(float v0, float v1) {
    unsigned h;
    asm("cvt.rn.f16x2.f32 %0, %1, %2;" : "=r"(h) : "f"(v1), "f"(v0));
    return h;
}
__device__ __forceinline__ unsigned cvt2_relu(float v0, float v1) {
    unsigned h = cvt2(v0, v1);
    unsigned r;
    asm("max.f16x2 %0, %1, %2;" : "=r"(r) : "r"(h), "r"(0u));
    return r;
}

// ============ main kernel: 3 point-tiles (48 points), single-fp16 weights ============
__global__ __launch_bounds__(128, 6)
void fields_mma_kernel(const float* __restrict__ x, float* __restrict__ out, int N)
{
    __shared__ __align__(16) unsigned char smem[IMG_BYTES];
    {
        const uint4* src = (const uint4*)g_img;
        uint4* dst = (uint4*)smem;
        for (int i = threadIdx.x; i < IMG_BYTES / 16; i += blockDim.x) dst[i] = src[i];
    }
    __syncthreads();

    const unsigned sbase = (unsigned)__cvta_generic_to_shared(smem);
    const float* sB2 = (const float*)(smem + B2_OFF);
    const float* sB3 = (const float*)(smem + B3_OFF);

    const int tid  = threadIdx.x;
    const int wid  = tid >> 5, lane = tid & 31;
    const int q    = lane & 3, r = lane >> 2;
    const unsigned lm_off = ((unsigned)(lane >> 3) << 7) + ((unsigned)(lane & 7) << 4);

    const int gwarp  = blockIdx.x * 4 + wid;
    const int nwarps = gridDim.x * 4;
    const int ntiles = (N + 47) / 48;            // 48 points per tile

    for (int tile = gwarp; tile < ntiles; tile += nwarps) {
        const int P = tile * 48;
        const int pA0 = P + r,      pA1 = P + r + 8;
        const int pB0 = P + r + 16, pB1 = P + r + 24;
        const int pC0 = P + r + 32, pC1 = P + r + 40;
        const bool iA0 = pA0 < N, iA1 = pA1 < N, iB0 = pB0 < N, iB1 = pB1 < N;
        const bool iC0 = pC0 < N, iC1 = pC1 < N;

        // ---- x A-fragments (single fp16): k = {x0,x1,x2,1,0,0,0,0} ----
        float a00 = 0.f, a01 = 0.f, a10 = 0.f, a11 = 0.f;
        float b00 = 0.f, b01 = 0.f, b10 = 0.f, b11 = 0.f;
        float c00 = 0.f, c01 = 0.f, c10 = 0.f, c11 = 0.f;
        if (q == 0) {
            if (iA0) { a00 = x[pA0]; a01 = x[N + pA0]; }
            if (iA1) { a10 = x[pA1]; a11 = x[N + pA1]; }
            if (iB0) { b00 = x[pB0]; b01 = x[N + pB0]; }
            if (iB1) { b10 = x[pB1]; b11 = x[N + pB1]; }
            if (iC0) { c00 = x[pC0]; c01 = x[N + pC0]; }
            if (iC1) { c10 = x[pC1]; c11 = x[N + pC1]; }
        } else if (q == 1) {
            if (iA0) { a00 = x[2 * N + pA0]; a01 = 1.0f; }
            if (iA1) { a10 = x[2 * N + pA1]; a11 = 1.0f; }
            if (iB0) { b00 = x[2 * N + pB0]; b01 = 1.0f; }
            if (iB1) { b10 = x[2 * N + pB1]; b11 = 1.0f; }
            if (iC0) { c00 = x[2 * N + pC0]; c01 = 1.0f; }
            if (iC1) { c10 = x[2 * N + pC1]; c11 = 1.0f; }
        }
        const unsigned xA0 = cvt2(a00, a01), xA1 = cvt2(a10, a11);
        const unsigned xB0 = cvt2(b00, b01), xB1 = cvt2(b10, b11);
        const unsigned xC0 = cvt2(c00, c01), xC1 = cvt2(c10, c11);

        #pragma unroll 1
        for (int d = 0; d < D_F; d++) {
            const unsigned fbase = sbase + (unsigned)(d * 2048);

            // ================= layer 1 (hi weights only) =================
            unsigned w1h0, w1h1;
            ldsm2(w1h0, w1h1, fbase + lm_off);
            float cA0[4] = {0, 0, 0, 0}, cA1[4] = {0, 0, 0, 0};
            float cB0[4] = {0, 0, 0, 0}, cB1[4] = {0, 0, 0, 0};
            float cC0[4] = {0, 0, 0, 0}, cC1[4] = {0, 0, 0, 0};
            mma_k8(cA0, xA0, xA1, w1h0);  mma_k8(cB0, xB0, xB1, w1h0);  mma_k8(cC0, xC0, xC1, w1h0);
            mma_k8(cA1, xA0, xA1, w1h1);  mma_k8(cB1, xB0, xB1, w1h1);  mma_k8(cC1, xC0, xC1, w1h1);

            unsigned aA[4], aB[4], aC[4];
            aA[0] = cvt2_relu(cA0[0], cA0[1]);  aA[1] = cvt2_relu(cA0[2], cA0[3]);
            aA[2] = cvt2_relu(cA1[0], cA1[1]);  aA[3] = cvt2_relu(cA1[2], cA1[3]);
            aB[0] = cvt2_relu(cB0[0], cB0[1]);  aB[1] = cvt2_relu(cB0[2], cB0[3]);
            aB[2] = cvt2_relu(cB1[0], cB1[1]);  aB[3] = cvt2_relu(cB1[2], cB1[3]);
            aC[0] = cvt2_relu(cC0[0], cC0[1]);  aC[1] = cvt2_relu(cC0[2], cC0[3]);
            aC[2] = cvt2_relu(cC1[0], cC1[1]);  aC[3] = cvt2_relu(cC1[2], cC1[3]);

            // ================= layer 2 (hi weights only) =================
            unsigned w2h0, w2h1, w2h2, w2h3;
            ldsm4(w2h0, w2h1, w2h2, w2h3, fbase + 512 + lm_off);
            float2 bn0 = *(const float2*)&sB2[d * 16 + 2 * q];
            float2 bn1 = *(const float2*)&sB2[d * 16 + 8 + 2 * q];
            float eA0[4] = {bn0.x, bn0.y, bn0.x, bn0.y};
            float eA1[4] = {bn1.x, bn1.y, bn1.x, bn1.y};
            float eB0[4] = {bn0.x, bn0.y, bn0.x, bn0.y};
            float eB1[4] = {bn1.x, bn1.y, bn1.x, bn1.y};
            float eC0[4] = {bn0.x, bn0.y, bn0.x, bn0.y};
            float eC1[4] = {bn1.x, bn1.y, bn1.x, bn1.y};
            mma_k16(eA0, aA, w2h0, w2h1);  mma_k16(eB0, aB, w2h0, w2h1);  mma_k16(eC0, aC, w2h0, w2h1);
            mma_k16(eA1, aA, w2h2, w2h3);  mma_k16(eB1, aB, w2h2, w2h3);  mma_k16(eC1, aC, w2h2, w2h3);

            unsigned gA[4], gB[4], gC[4];
            gA[0] = cvt2_relu(eA0[0], eA0[1]);  gA[1] = cvt2_relu(eA0[2], eA0[3]);
            gA[2] = cvt2_relu(eA1[0], eA1[1]);  gA[3] = cvt2_relu(eA1[2], eA1[3]);
            gB[0] = cvt2_relu(eB0[0], eB0[1]);  gB[1] = cvt2_relu(eB0[2], eB0[3]);
            gB[2] = cvt2_relu(eB1[0], eB1[1]);  gB[3] = cvt2_relu(eB1[2], eB1[3]);
            gC[0] = cvt2_relu(eC0[0], eC0[1]);  gC[1] = cvt2_relu(eC0[2], eC0[3]);
            gC[2] = cvt2_relu(eC1[0], eC1[1]);  gC[3] = cvt2_relu(eC1[2], eC1[3]);

            // ================= layer 3 (hi only) =================
            unsigned w3h0, w3h1;
            ldsm2(w3h0, w3h1, fbase + 1536 + lm_off);
            float2 b3v = *(const float2*)&sB3[d * 8 + 2 * q];
            float fA[4] = {b3v.x, b3v.y, b3v.x, b3v.y};
            float fB[4] = {b3v.x, b3v.y, b3v.x, b3v.y};
            float fC[4] = {b3v.x, b3v.y, b3v.x, b3v.y};
            mma_k16(fA, gA, w3h0, w3h1);  mma_k16(fB, gB, w3h0, w3h1);  mma_k16(fC, gC, w3h0, w3h1);

            // ---- store ----
            const int o0 = 2 * q, o1 = 2 * q + 1;
            if (o0 < 3) {
                float* rowp = out + (size_t)(d * 3 + o0) * N;
                if (iA0) rowp[pA0] = fA[0];
                if (iA1) rowp[pA1] = fA[2];
                if (iB0) rowp[pB0] = fB[0];
                if (iB1) rowp[pB1] = fB[2];
                if (iC0) rowp[pC0] = fC[0];
                if (iC1) rowp[pC1] = fC[2];
            }
            if (o1 < 3) {
                float* rowp = out + (size_t)(d * 3 + o1) * N;
                if (iA0) rowp[pA0] = fA[1];
                if (iA1) rowp[pA1] = fA[3];
                if (iB0) rowp[pB0] = fB[1];
                if (iB1) rowp[pB1] = fB[3];
                if (iC0) rowp[pC0] = fC[1];
                if (iC1) rowp[pC1] = fC[3];
            }
        }
    }
}

extern "C" void kernel_launch(void* const* d_in, const int* in_sizes, int n_in,
                              void* d_out, int out_size)
{
    const float* x  = (const float*)d_in[0];
    const float* W1 = (const float*)d_in[1];
    const float* b1 = (const float*)d_in[2];
    const float* W2 = (const float*)d_in[3];
    const float* b2 = (const float*)d_in[4];
    const float* W3 = (const float*)d_in[5];
    const float* b3 = (const float*)d_in[6];
    float* out = (float*)d_out;

    const int N = in_sizes[0] / 3;   // x is [1,3,N]

    prep_kernel<<<(8576 + 255) / 256, 256>>>(W1, b1, W2, b2, W3, b3);

    // 6 CTAs/SM x 128 threads on 152 SMs (grid-stride safe)
    fields_mma_kernel<<<912, 128>>>(x, out, N);
}